// round 12
// baseline (speedup 1.0000x reference)
#include <cuda_runtime.h>
#include <math.h>

#define BB 16
#define NN 8
#define TT 65536
#define CHUNKS 32
#define TPB 256
#define TPC (TT / CHUNKS)        // 2048 floats per chunk per row
#define SCOL4 128                // float4 columns per stage (512 floats)
#define SUB ((TPC / 4) / SCOL4)  // 4 stages per chunk
#define NSTAGE 3
#define NCELL (NN * NN)          // 64

// Scratch: [BB][64 cells][CHUNKS] -> cross-chunk sum is contiguous (float4-able).
__device__ float g_part[BB * NCELL * CHUNKS];
__device__ unsigned int g_ctr;   // zero-initialized; last block resets to 0

__device__ __forceinline__ void cp16(void* sdst, const void* gsrc) {
    unsigned int sa = (unsigned int)__cvta_generic_to_shared(sdst);
    asm volatile("cp.async.cg.shared.global [%0], [%1], 16;" :: "r"(sa), "l"(gsrc) : "memory");
}
__device__ __forceinline__ void cp_commit() {
    asm volatile("cp.async.commit_group;" ::: "memory");
}
template <int N> __device__ __forceinline__ void cp_wait() {
    asm volatile("cp.async.wait_group %0;" :: "n"(N) : "memory");
}

__global__ __launch_bounds__(TPB, 4)
void sp_fused(const float* __restrict__ inp, const float* __restrict__ tgt,
              float* __restrict__ out, int out_size) {
    const int b = blockIdx.y;
    const int chunk = blockIdx.x;
    const int tid = threadIdx.x;
    const int col0 = tid & 63;     // base float4 column (handles col0 and col0+64)
    const int g = tid >> 6;        // i-group: X rows {2g, 2g+1}; Y coop rows {g, g+4}
    const int warp = tid >> 5;
    const int lane = tid & 31;

    const float4* __restrict__ X = reinterpret_cast<const float4*>(inp)
                                   + (size_t)b * NN * (TT / 4) + (size_t)chunk * (TPC / 4);
    const float4* __restrict__ Y = reinterpret_cast<const float4*>(tgt)
                                   + (size_t)b * NN * (TT / 4) + (size_t)chunk * (TPC / 4);

    __shared__ float4 ybuf[NSTAGE][NN][SCOL4];   // 48 KB, triple-buffered Y stage
    __shared__ float sred[TPB / 32][16];

    const float4* __restrict__ Yg0 = Y + (size_t)g * (TT / 4);
    const float4* __restrict__ Yg1 = Y + (size_t)(g + 4) * (TT / 4);
    const float4* __restrict__ Xr0 = X + (size_t)(2 * g) * (TT / 4);
    const float4* __restrict__ Xr1 = X + (size_t)(2 * g + 1) * (TT / 4);

    // ---- Prologue: issue Y stages 0 and 1 via cp.async, then X stage 0 ----
#pragma unroll
    for (int s = 0; s < 2; s++) {
        const int t4 = s * SCOL4;
        cp16(&ybuf[s][g][col0],      &Yg0[t4 + col0]);
        cp16(&ybuf[s][g][col0 + 64], &Yg0[t4 + col0 + 64]);
        cp16(&ybuf[s][g + 4][col0],      &Yg1[t4 + col0]);
        cp16(&ybuf[s][g + 4][col0 + 64], &Yg1[t4 + col0 + 64]);
        cp_commit();
    }

    float acc[2][NN];
#pragma unroll
    for (int i = 0; i < 2; i++)
#pragma unroll
        for (int j = 0; j < NN; j++) acc[i][j] = 0.f;

    float4 xc00 = __ldg(&Xr0[col0]);
    float4 xc01 = __ldg(&Xr0[col0 + 64]);
    float4 xc10 = __ldg(&Xr1[col0]);
    float4 xc11 = __ldg(&Xr1[col0 + 64]);

    // ---- Main pipeline: wait -> barrier -> issue s+2 -> prefetch X -> compute ----
#pragma unroll
    for (int s = 0; s < SUB; s++) {
        if (s == SUB - 1) cp_wait<0>(); else cp_wait<1>();
        __syncthreads();   // stage s visible to all; buffer (s+2)%3 fully consumed

        if (s + 2 < SUB) {
            const int t4 = (s + 2) * SCOL4;
            const int buf = (s + 2) % NSTAGE;
            cp16(&ybuf[buf][g][col0],      &Yg0[t4 + col0]);
            cp16(&ybuf[buf][g][col0 + 64], &Yg0[t4 + col0 + 64]);
            cp16(&ybuf[buf][g + 4][col0],      &Yg1[t4 + col0]);
            cp16(&ybuf[buf][g + 4][col0 + 64], &Yg1[t4 + col0 + 64]);
            cp_commit();
        }

        float4 xn00, xn01, xn10, xn11;
        if (s + 1 < SUB) {
            const int t4 = (s + 1) * SCOL4;
            xn00 = __ldg(&Xr0[t4 + col0]);
            xn01 = __ldg(&Xr0[t4 + col0 + 64]);
            xn10 = __ldg(&Xr1[t4 + col0]);
            xn11 = __ldg(&Xr1[t4 + col0 + 64]);
        }

        const float4 (*yb)[SCOL4] = ybuf[s % NSTAGE];
#pragma unroll
        for (int h = 0; h < 2; h++) {
            const int c = col0 + h * 64;
            const float4 x0 = h ? xc01 : xc00;
            const float4 x1 = h ? xc11 : xc10;
#pragma unroll
            for (int j = 0; j < NN; j++) {
                const float4 y = yb[j][c];
                float d;
                d = x0.x - y.x; acc[0][j] = fmaf(d, d, acc[0][j]);
                d = x0.y - y.y; acc[0][j] = fmaf(d, d, acc[0][j]);
                d = x0.z - y.z; acc[0][j] = fmaf(d, d, acc[0][j]);
                d = x0.w - y.w; acc[0][j] = fmaf(d, d, acc[0][j]);
                d = x1.x - y.x; acc[1][j] = fmaf(d, d, acc[1][j]);
                d = x1.y - y.y; acc[1][j] = fmaf(d, d, acc[1][j]);
                d = x1.z - y.z; acc[1][j] = fmaf(d, d, acc[1][j]);
                d = x1.w - y.w; acc[1][j] = fmaf(d, d, acc[1][j]);
            }
        }
        if (s + 1 < SUB) {
            xc00 = xn00; xc01 = xn01; xc10 = xn10; xc11 = xn11;
        }
    }

    // ---- Reduce 16 accumulators within warp, then across warps ----
#pragma unroll
    for (int i = 0; i < 2; i++)
#pragma unroll
        for (int j = 0; j < NN; j++) {
            float v = acc[i][j];
            v += __shfl_xor_sync(0xffffffffu, v, 16);
            v += __shfl_xor_sync(0xffffffffu, v, 8);
            v += __shfl_xor_sync(0xffffffffu, v, 4);
            v += __shfl_xor_sync(0xffffffffu, v, 2);
            v += __shfl_xor_sync(0xffffffffu, v, 1);
            acc[i][j] = v;
        }
    if (lane == 0) {
#pragma unroll
        for (int i = 0; i < 2; i++)
#pragma unroll
            for (int j = 0; j < NN; j++) sred[warp][i * NN + j] = acc[i][j];
    }
    __syncthreads();
    // Cell (i,j): i-group g=i>>1 lives in warps {2g, 2g+1}.
    if (tid < NCELL) {
        const int ci = tid >> 3, cj = tid & 7;
        const int cg = ci >> 1, cii = ci & 1;
        const float s = sred[2 * cg][cii * NN + cj] + sred[2 * cg + 1][cii * NN + cj];
        g_part[(b * NCELL + tid) * CHUNKS + chunk] = s;
    }

    // ---- Arrival counter: last of 512 blocks finishes the job ----
    __shared__ unsigned int s_last;
    if (tid == 0) {
        __threadfence();
        s_last = (atomicAdd(&g_ctr, 1u) == (unsigned)(CHUNKS * BB - 1)) ? 1u : 0u;
    }
    __syncthreads();
    if (!s_last) return;
    if (tid == 0) g_ctr = 0;       // reset for next graph replay

    // ---- Phase 2 (last block only): chunk reduction, L1-bypass loads ----
    float* s_pl = reinterpret_cast<float*>(ybuf);   // reuse stage smem
    for (int cell = tid; cell < BB * NCELL; cell += TPB) {
        const float4* p = reinterpret_cast<const float4*>(&g_part[cell * CHUNKS]);
        float4 a = __ldcv(p + 0);
        float s = a.x + a.y + a.z + a.w;
#pragma unroll
        for (int q = 1; q < CHUNKS / 4; q++) {
            const float4 v = __ldcv(p + q);
            s += v.x + v.y + v.z + v.w;
        }
        s_pl[cell] = s * (1.0f / (float)TT);
    }
    __syncthreads();

    // ---- Phase 3: Sinkhorn (threads 0..127; thread = (batch, column j)) ----
    float loss_t = 0.f;
    int aj[NN];
    const int sb = tid >> 3;
    const int sj = tid & 7;

    if (tid < 128) {
        float pl[NN], z[NN];
#pragma unroll
        for (int i = 0; i < NN; i++) {
            pl[i] = s_pl[sb * NCELL + i * NN + sj];
            z[i] = -pl[i];         // COLDNESS = 1
        }

#pragma unroll 1
        for (int it = 0; it < 10; it++) {
            float s = 0.f;
#pragma unroll
            for (int i = 0; i < NN; i++) s += __expf(z[i]);
            const float l = __logf(s);
#pragma unroll
            for (int i = 0; i < NN; i++) z[i] -= l;
            float e[NN];
#pragma unroll
            for (int i = 0; i < NN; i++) e[i] = __expf(z[i]);
#pragma unroll
            for (int off = 1; off < NN; off <<= 1)
#pragma unroll
                for (int i = 0; i < NN; i++)
                    e[i] += __shfl_xor_sync(0xffffffffu, e[i], off);
#pragma unroll
            for (int i = 0; i < NN; i++) z[i] -= __logf(e[i]);
        }

#pragma unroll
        for (int i = 0; i < NN; i++)
            loss_t += (pl[i] + z[i]) * __expf(z[i]);

        float av[NN];
#pragma unroll
        for (int i = 0; i < NN; i++) { av[i] = z[i]; aj[i] = sj; }
#pragma unroll
        for (int off = 1; off < NN; off <<= 1)
#pragma unroll
            for (int i = 0; i < NN; i++) {
                const float ov = __shfl_xor_sync(0xffffffffu, av[i], off);
                const int oj = __shfl_xor_sync(0xffffffffu, aj[i], off);
                if (ov > av[i] || (ov == av[i] && oj < aj[i])) { av[i] = ov; aj[i] = oj; }
            }
    }

    __shared__ float s_wloss[TPB / 32];
#pragma unroll
    for (int off = 16; off; off >>= 1)
        loss_t += __shfl_xor_sync(0xffffffffu, loss_t, off);
    if (lane == 0) s_wloss[warp] = loss_t;
    __syncthreads();
    float loss = 0.f;
    if (tid == 0) {
#pragma unroll
        for (int w = 0; w < 4; w++) loss += s_wloss[w];
        loss *= (1.0f / (float)BB);
    }

    // ---- Output: loss then pattern (fp32); defensive layouts ----
    const int full = 1 + BB * NN;   // 129
    if (out_size >= full) {
        if (tid == 0) out[0] = loss;
        if (tid < 128 && sj == 0) {
#pragma unroll
            for (int i = 0; i < NN; i++) out[1 + sb * NN + i] = (float)aj[i];
        }
        for (int idx = full + tid; idx < out_size; idx += TPB) out[idx] = 0.f;
    } else if (out_size == BB * NN) {
        if (tid < 128 && sj == 0) {
#pragma unroll
            for (int i = 0; i < NN; i++) out[sb * NN + i] = (float)aj[i];
        }
    } else {
        if (tid == 0 && out_size > 0) out[0] = loss;
        for (int idx = 1 + tid; idx < out_size; idx += TPB) out[idx] = 0.f;
    }
}

extern "C" void kernel_launch(void* const* d_in, const int* in_sizes, int n_in,
                              void* d_out, int out_size) {
    const float* inp = (const float*)d_in[0];
    const float* tgt = (const float*)d_in[1];

    dim3 grid(CHUNKS, BB);
    sp_fused<<<grid, TPB>>>(inp, tgt, (float*)d_out, out_size);
}